// round 7
// baseline (speedup 1.0000x reference)
#include <cuda_runtime.h>
#include <math.h>

#define DIMK 512
#define HD   1024

typedef unsigned long long ull;

// Scratch (device globals). k-split partial results (A: k<256, B: k>=256).
__device__ __align__(16) float g_causA[64 * HD];
__device__ __align__(16) float g_causB[64 * HD];
__device__ __align__(16) float g_effA [64 * HD];
__device__ __align__(16) float g_effB [64 * HD];
__device__ __align__(16) float g_ctxTA[HD * 64];   // transposed [h][b], k-half A
__device__ __align__(16) float g_ctxTB[HD * 64];   // transposed [h][b], k-half B

// ---------------------------------------------------------------------------
// Phase 1: three 64x512 @ 512x1024 GEMMs, all k-split in halves.
// ---------------------------------------------------------------------------
__global__ void __launch_bounds__(256) gemm_kernel(
    const float* __restrict__ state, const float* __restrict__ action,
    const float* __restrict__ embed, const float* __restrict__ W1,
    const float* __restrict__ b1)
{
    const int slot    = blockIdx.y;
    const int colbase = (blockIdx.x >> 1) * 32;
    const int kbase   = (blockIdx.x & 1) * 256;

    const float* W = W1 + slot * DIMK * HD;

    __shared__ float Xs[64][132];

    const int tid = threadIdx.x;
    const int tx  = tid & 15;
    const int ty  = tid >> 4;

    float acc[4][2] = {};

    for (int kt = kbase; kt < kbase + 256; kt += 128) {
        for (int lin = tid; lin < 64 * 32; lin += 256) {
            int row = lin >> 5;
            int q   = lin & 31;
            int gc  = kt + q * 4;
            float4 v;
            if (slot < 2) {
                v = *reinterpret_cast<const float4*>(embed + row * DIMK + gc);
            } else {
                float4 s4 = *reinterpret_cast<const float4*>(state  + row * DIMK + gc);
                float4 a4 = *reinterpret_cast<const float4*>(action + row * DIMK + gc);
                v = make_float4(s4.x + a4.x, s4.y + a4.y, s4.z + a4.z, s4.w + a4.w);
            }
            *reinterpret_cast<float4*>(&Xs[row][q * 4]) = v;
        }
        __syncthreads();

        #pragma unroll 8
        for (int k = 0; k < 128; k++) {
            float2 w = *reinterpret_cast<const float2*>(W + (kt + k) * HD + colbase + 2 * tx);
            #pragma unroll
            for (int r = 0; r < 4; r++) {
                float xv = Xs[ty + 16 * r][k];
                acc[r][0] = fmaf(xv, w.x, acc[r][0]);
                acc[r][1] = fmaf(xv, w.y, acc[r][1]);
            }
        }
        __syncthreads();
    }

    const int isA = (kbase == 0);
    #pragma unroll
    for (int r = 0; r < 4; r++) {
        int row = ty + 16 * r;
        int c0  = colbase + 2 * tx;
        if (slot == 0) {
            float v0 = acc[r][0], v1 = acc[r][1];
            if (isA) { v0 += b1[c0]; v1 += b1[c0 + 1]; }
            float* dst = isA ? g_causA : g_causB;
            dst[row * HD + c0]     = v0;
            dst[row * HD + c0 + 1] = v1;
        } else if (slot == 1) {
            float* dst = isA ? g_effA : g_effB;
            dst[row * HD + c0]     = acc[r][0];
            dst[row * HD + c0 + 1] = acc[r][1];
        } else {
            float* dst = isA ? g_ctxTA : g_ctxTB;
            dst[c0 * 64 + row]       = acc[r][0];
            dst[(c0 + 1) * 64 + row] = acc[r][1];
        }
    }
}

// ---------------------------------------------------------------------------
// f32x2 packed helpers
// ---------------------------------------------------------------------------
__device__ __forceinline__ ull pack2(float a, float b) {
    ull r;
    asm("mov.b64 %0, {%1, %2};" : "=l"(r)
        : "r"(__float_as_uint(a)), "r"(__float_as_uint(b)));
    return r;
}
__device__ __forceinline__ void unpack2(ull v, float& a, float& b) {
    unsigned int x, y;
    asm("mov.b64 {%0, %1}, %2;" : "=r"(x), "=r"(y) : "l"(v));
    a = __uint_as_float(x); b = __uint_as_float(y);
}
__device__ __forceinline__ ull add2(ull a, ull b) {
    ull r; asm("add.rn.f32x2 %0, %1, %2;" : "=l"(r) : "l"(a), "l"(b)); return r;
}
__device__ __forceinline__ ull mul2(ull a, ull b) {
    ull r; asm("mul.rn.f32x2 %0, %1, %2;" : "=l"(r) : "l"(a), "l"(b)); return r;
}
__device__ __forceinline__ ull fma2(ull a, ull b, ull c) {
    ull r; asm("fma.rn.f32x2 %0, %1, %2, %3;" : "=l"(r) : "l"(a), "l"(b), "l"(c)); return r;
}

// ---------------------------------------------------------------------------
// Phase 2: NO transcendentals. GELU via degree-13 odd erf polynomial:
//   Phi(x) ~= 0.5 + s*q(s^2),  s = clamp(x, +-sqrt(13)),  q = deg-6 in u=s^2
//   gelu(x)*w = (x*w) * Phi(x)
// Hand-fit Newton interpolation on u in [0,13] (nodes 0,0.7,2.2,4.6,7.6,10.8,13).
// Per warp-k: 11 FFMA2 + ~6 ALU (clamp) + 2.5 LDS, zero MUFU.
// ---------------------------------------------------------------------------
#define QA0 0.3989423f
#define QA1 -0.06645146f
#define QA2 9.86522e-3f
#define QA3 -1.1015013e-3f
#define QA4 8.54950e-5f
#define QA5 -3.97013e-6f
#define QA6 8.04597e-8f
#define CLMP 3.6055513f

__global__ void __launch_bounds__(256) score_kernel(
    const float* __restrict__ W2, const float* __restrict__ b2,
    float* __restrict__ out)
{
    extern __shared__ float sm[];
    float* caus_s = sm;              // 2 * 1024
    float* eff_s  = sm + 2048;       // 4 * 1024
    float* w2p    = sm + 6144;       // 2048 (1024 pairs, duplicated)
    float* ctx_s  = sm + 8192;       // 64 * 64

    const int tid = threadIdx.x;
    const int i0  = (blockIdx.x >> 4) * 2;   // 32 i-tiles
    const int j0  = (blockIdx.x & 15) * 4;   // 16 j-tiles

    for (int lin = tid; lin < 2048; lin += 256) {
        int r = lin >> 10, c = lin & 1023;
        caus_s[lin] = g_causA[(i0 + r) * HD + c] + g_causB[(i0 + r) * HD + c];
    }
    for (int lin = tid; lin < 4096; lin += 256) {
        int r = lin >> 10, c = lin & 1023;
        eff_s[lin]  = g_effA[(j0 + r) * HD + c] + g_effB[(j0 + r) * HD + c];
    }
    for (int lin = tid; lin < 1024; lin += 256) {
        float v = W2[lin];
        w2p[2 * lin]     = v;
        w2p[2 * lin + 1] = v;
    }

    const int w    = tid >> 5;
    const int lane = tid & 31;
    const int wi   = w >> 2, wj = w & 3;
    const float* cs = caus_s + wi * 1024;
    const float* es = eff_s  + wj * 1024;
    const ull*  ctxp = reinterpret_cast<const ull*>(ctx_s);

    const ull K6 = pack2(QA6, QA6), K5 = pack2(QA5, QA5), K4 = pack2(QA4, QA4);
    const ull K3 = pack2(QA3, QA3), K2 = pack2(QA2, QA2), K1 = pack2(QA1, QA1);
    const ull K0 = pack2(QA0, QA0);
    const ull HALF2 = pack2(0.5f, 0.5f);
    ull acc = pack2(0.f, 0.f);

    for (int ht = 0; ht < HD; ht += 64) {
        __syncthreads();   // covers initial staging on first iter
        for (int lin = tid * 4; lin < 64 * 64; lin += 256 * 4) {
            float4 a4 = *reinterpret_cast<const float4*>(g_ctxTA + ht * 64 + lin);
            float4 b4 = *reinterpret_cast<const float4*>(g_ctxTB + ht * 64 + lin);
            *reinterpret_cast<float4*>(ctx_s + lin) =
                make_float4(a4.x + b4.x, a4.y + b4.y, a4.z + b4.z, a4.w + b4.w);
        }
        __syncthreads();

        const float* w2row = w2p + 2 * ht;
        #pragma unroll 4
        for (int k = 0; k < 64; k += 4) {
            float4 cv = *reinterpret_cast<const float4*>(cs + ht + k);
            float4 ev = *reinterpret_cast<const float4*>(es + ht + k);
            float ce[4] = {cv.x + ev.x, cv.y + ev.y, cv.z + ev.z, cv.w + ev.w};
            #pragma unroll
            for (int q = 0; q < 4; q++) {
                ull ce2 = pack2(ce[q], ce[q]);
                ull hw2 = *reinterpret_cast<const ull*>(w2row + 2 * (k + q));
                ull c2  = ctxp[(k + q) * 32 + lane];
                ull x2  = add2(ce2, c2);
                // clamp (scalar ALU: FMNMX on |x| + copysign)
                float xa, xb; unpack2(x2, xa, xb);
                float sa = copysignf(fminf(fabsf(xa), CLMP), xa);
                float sb = copysignf(fminf(fabsf(xb), CLMP), xb);
                ull s2 = pack2(sa, sb);
                ull u2 = mul2(s2, s2);
                // Horner deg-6 in u
                ull q2 = fma2(K6, u2, K5);
                q2 = fma2(q2, u2, K4);
                q2 = fma2(q2, u2, K3);
                q2 = fma2(q2, u2, K2);
                q2 = fma2(q2, u2, K1);
                q2 = fma2(q2, u2, K0);
                ull phi2 = fma2(s2, q2, HALF2);
                ull xw2  = mul2(x2, hw2);
                acc = fma2(xw2, phi2, acc);
            }
        }
    }

    float a0, a1; unpack2(acc, a0, a1);
    float bb = b2[0];
    float s = 1.0f / (1.0f + expf(-(a0 + bb)))
            + 1.0f / (1.0f + expf(-(a1 + bb)));
    #pragma unroll
    for (int off = 16; off; off >>= 1)
        s += __shfl_down_sync(0xffffffffu, s, off);
    if (lane == 0)
        out[(i0 + wi) * 64 + (j0 + wj)] = s * (1.0f / 64.0f);
}

// ---------------------------------------------------------------------------
extern "C" void kernel_launch(void* const* d_in, const int* in_sizes, int n_in,
                              void* d_out, int out_size)
{
    const float* state  = (const float*)d_in[0];
    const float* action = (const float*)d_in[1];
    const float* embed  = (const float*)d_in[2];
    const float* W1     = (const float*)d_in[3];
    const float* b1     = (const float*)d_in[4];
    const float* W2     = (const float*)d_in[5];
    const float* b2     = (const float*)d_in[6];
    float* out = (float*)d_out;

    dim3 g1(64, 3);
    gemm_kernel<<<g1, 256>>>(state, action, embed, W1, b1);

    const int smem = (2048 + 4096 + 2048 + 4096) * sizeof(float); // 49152 B
    cudaFuncSetAttribute(score_kernel, cudaFuncAttributeMaxDynamicSharedMemorySize, smem);
    score_kernel<<<512, 256, smem>>>(W2, b2, out);
}

// round 8
// speedup vs baseline: 1.1551x; 1.1551x over previous
#include <cuda_runtime.h>
#include <math.h>

#define DIMK 512
#define HD   1024

typedef unsigned long long ull;

// Scratch (device globals). k-split partial results (A: k<256, B: k>=256).
__device__ __align__(16) float g_causA[64 * HD];
__device__ __align__(16) float g_causB[64 * HD];
__device__ __align__(16) float g_effA [64 * HD];
__device__ __align__(16) float g_effB [64 * HD];
__device__ __align__(16) float g_ctxTA[HD * 64];   // transposed [h][b], k-half A
__device__ __align__(16) float g_ctxTB[HD * 64];   // transposed [h][b], k-half B
// separable linear parts:  sum_h caus[i,h]*w'_h, etc., with w' = 0.5*W2
__device__ float g_A[64];
__device__ float g_B[64];
__device__ float g_C[64];

// ---------------------------------------------------------------------------
// Phase 1: three 64x512 @ 512x1024 GEMMs, all k-split in halves.
// ---------------------------------------------------------------------------
__global__ void __launch_bounds__(256) gemm_kernel(
    const float* __restrict__ state, const float* __restrict__ action,
    const float* __restrict__ embed, const float* __restrict__ W1,
    const float* __restrict__ b1)
{
    const int slot    = blockIdx.y;
    const int colbase = (blockIdx.x >> 1) * 32;
    const int kbase   = (blockIdx.x & 1) * 256;

    const float* W = W1 + slot * DIMK * HD;

    __shared__ float Xs[64][132];

    const int tid = threadIdx.x;
    const int tx  = tid & 15;
    const int ty  = tid >> 4;

    float acc[4][2] = {};

    for (int kt = kbase; kt < kbase + 256; kt += 128) {
        for (int lin = tid; lin < 64 * 32; lin += 256) {
            int row = lin >> 5;
            int q   = lin & 31;
            int gc  = kt + q * 4;
            float4 v;
            if (slot < 2) {
                v = *reinterpret_cast<const float4*>(embed + row * DIMK + gc);
            } else {
                float4 s4 = *reinterpret_cast<const float4*>(state  + row * DIMK + gc);
                float4 a4 = *reinterpret_cast<const float4*>(action + row * DIMK + gc);
                v = make_float4(s4.x + a4.x, s4.y + a4.y, s4.z + a4.z, s4.w + a4.w);
            }
            *reinterpret_cast<float4*>(&Xs[row][q * 4]) = v;
        }
        __syncthreads();

        #pragma unroll 8
        for (int k = 0; k < 128; k++) {
            float2 w = *reinterpret_cast<const float2*>(W + (kt + k) * HD + colbase + 2 * tx);
            #pragma unroll
            for (int r = 0; r < 4; r++) {
                float xv = Xs[ty + 16 * r][k];
                acc[r][0] = fmaf(xv, w.x, acc[r][0]);
                acc[r][1] = fmaf(xv, w.y, acc[r][1]);
            }
        }
        __syncthreads();
    }

    const int isA = (kbase == 0);
    #pragma unroll
    for (int r = 0; r < 4; r++) {
        int row = ty + 16 * r;
        int c0  = colbase + 2 * tx;
        if (slot == 0) {
            float v0 = acc[r][0], v1 = acc[r][1];
            if (isA) { v0 += b1[c0]; v1 += b1[c0 + 1]; }
            float* dst = isA ? g_causA : g_causB;
            dst[row * HD + c0]     = v0;
            dst[row * HD + c0 + 1] = v1;
        } else if (slot == 1) {
            float* dst = isA ? g_effA : g_effB;
            dst[row * HD + c0]     = acc[r][0];
            dst[row * HD + c0 + 1] = acc[r][1];
        } else {
            float* dst = isA ? g_ctxTA : g_ctxTB;
            dst[c0 * 64 + row]       = acc[r][0];
            dst[(c0 + 1) * 64 + row] = acc[r][1];
        }
    }
}

// ---------------------------------------------------------------------------
// Phase 1.5: separable linear parts A_i, B_j, C_b  (w' = 0.5*W2)
// grid = 3 blocks x 256 threads. Trivial cost (~200k FLOP).
// ---------------------------------------------------------------------------
__global__ void __launch_bounds__(256) pre_kernel(const float* __restrict__ W2)
{
    const int slot = blockIdx.x;
    const int tid  = threadIdx.x;
    if (slot < 2) {
        const float* PA = slot == 0 ? g_causA : g_effA;
        const float* PB = slot == 0 ? g_causB : g_effB;
        float* dst = slot == 0 ? g_A : g_B;
        int w = tid >> 5, lane = tid & 31;
        #pragma unroll
        for (int m = 0; m < 8; m++) {
            int row = w * 8 + m;
            float s = 0.f;
            for (int h = lane; h < HD; h += 32)
                s += (PA[row * HD + h] + PB[row * HD + h]) * (0.5f * W2[h]);
            #pragma unroll
            for (int off = 16; off; off >>= 1)
                s += __shfl_down_sync(0xffffffffu, s, off);
            if (lane == 0) dst[row] = s;
        }
    } else {
        __shared__ float red[256];
        int b = tid & 63, part = tid >> 6;
        float s = 0.f;
        for (int h = part * 256; h < part * 256 + 256; h++)
            s += (g_ctxTA[h * 64 + b] + g_ctxTB[h * 64 + b]) * (0.5f * W2[h]);
        red[tid] = s;
        __syncthreads();
        if (tid < 64)
            g_C[tid] = red[tid] + red[tid + 64] + red[tid + 128] + red[tid + 192];
    }
}

// ---------------------------------------------------------------------------
// f32x2 packed helpers
// ---------------------------------------------------------------------------
__device__ __forceinline__ ull pack2(float a, float b) {
    ull r;
    asm("mov.b64 %0, {%1, %2};" : "=l"(r)
        : "r"(__float_as_uint(a)), "r"(__float_as_uint(b)));
    return r;
}
__device__ __forceinline__ void unpack2(ull v, float& a, float& b) {
    unsigned int x, y;
    asm("mov.b64 {%0, %1}, %2;" : "=r"(x), "=r"(y) : "l"(v));
    a = __uint_as_float(x); b = __uint_as_float(y);
}
__device__ __forceinline__ ull add2(ull a, ull b) {
    ull r; asm("add.rn.f32x2 %0, %1, %2;" : "=l"(r) : "l"(a), "l"(b)); return r;
}
__device__ __forceinline__ ull mul2(ull a, ull b) {
    ull r; asm("mul.rn.f32x2 %0, %1, %2;" : "=l"(r) : "l"(a), "l"(b)); return r;
}
__device__ __forceinline__ ull fma2(ull a, ull b, ull c) {
    ull r; asm("fma.rn.f32x2 %0, %1, %2, %3;" : "=l"(r) : "l"(a), "l"(b), "l"(c)); return r;
}
__device__ __forceinline__ float tanh_ap(float x) {
    float r; asm("tanh.approx.f32 %0, %1;" : "=f"(r) : "f"(x)); return r;
}

// ---------------------------------------------------------------------------
// Phase 2: logit = (A_i + B_j + C_b + b2) + sum_h xw'*tanh(...)
// Inner loop: 6 f32x2 + 2 tanh per lane-k (linear part hoisted out).
// ---------------------------------------------------------------------------
__global__ void __launch_bounds__(256) score_kernel(
    const float* __restrict__ W2, const float* __restrict__ b2,
    float* __restrict__ out)
{
    extern __shared__ float sm[];
    float* caus_s = sm;              // 2 * 1024
    float* eff_s  = sm + 2048;       // 4 * 1024
    float* w2p    = sm + 6144;       // 2048 (1024 pairs of 0.5*W2, duplicated)
    float* ctx_s  = sm + 8192;       // 64 * 64

    const int tid = threadIdx.x;
    const int i0  = (blockIdx.x >> 4) * 2;   // 32 i-tiles
    const int j0  = (blockIdx.x & 15) * 4;   // 16 j-tiles

    for (int lin = tid; lin < 2048; lin += 256) {
        int r = lin >> 10, c = lin & 1023;
        caus_s[lin] = g_causA[(i0 + r) * HD + c] + g_causB[(i0 + r) * HD + c];
    }
    for (int lin = tid; lin < 4096; lin += 256) {
        int r = lin >> 10, c = lin & 1023;
        eff_s[lin]  = g_effA[(j0 + r) * HD + c] + g_effB[(j0 + r) * HD + c];
    }
    for (int lin = tid; lin < 1024; lin += 256) {
        float v = 0.5f * W2[lin];
        w2p[2 * lin]     = v;
        w2p[2 * lin + 1] = v;
    }

    const int w    = tid >> 5;
    const int lane = tid & 31;
    const int wi   = w >> 2, wj = w & 3;
    const float* cs = caus_s + wi * 1024;
    const float* es = eff_s  + wj * 1024;
    const ull*  ctxp = reinterpret_cast<const ull*>(ctx_s);

    const ull C0 = pack2(0.7978845608f, 0.7978845608f);
    const ull C1 = pack2(0.0356774081f, 0.0356774081f);
    ull acc = pack2(0.f, 0.f);

    for (int ht = 0; ht < HD; ht += 64) {
        __syncthreads();   // covers initial staging on first iter
        for (int lin = tid * 4; lin < 64 * 64; lin += 256 * 4) {
            float4 a4 = *reinterpret_cast<const float4*>(g_ctxTA + ht * 64 + lin);
            float4 b4 = *reinterpret_cast<const float4*>(g_ctxTB + ht * 64 + lin);
            *reinterpret_cast<float4*>(ctx_s + lin) =
                make_float4(a4.x + b4.x, a4.y + b4.y, a4.z + b4.z, a4.w + b4.w);
        }
        __syncthreads();

        const float* w2row = w2p + 2 * ht;
        #pragma unroll 4
        for (int k = 0; k < 64; k += 4) {
            float4 cv = *reinterpret_cast<const float4*>(cs + ht + k);
            float4 ev = *reinterpret_cast<const float4*>(es + ht + k);
            float ce[4] = {cv.x + ev.x, cv.y + ev.y, cv.z + ev.z, cv.w + ev.w};
            #pragma unroll
            for (int q = 0; q < 4; q++) {
                ull ce2 = pack2(ce[q], ce[q]);
                ull hw2 = *reinterpret_cast<const ull*>(w2row + 2 * (k + q));
                ull c2  = ctxp[(k + q) * 32 + lane];
                ull x2  = add2(ce2, c2);
                ull u2  = mul2(x2, x2);
                ull p2  = fma2(u2, C1, C0);
                ull in2 = mul2(x2, p2);
                float ia, ib; unpack2(in2, ia, ib);
                ull t2  = pack2(tanh_ap(ia), tanh_ap(ib));
                ull xw2 = mul2(x2, hw2);
                acc = fma2(xw2, t2, acc);     // linear part hoisted to A/B/C
            }
        }
    }

    float a0, a1; unpack2(acc, a0, a1);
    float base = g_A[i0 + wi] + g_B[j0 + wj] + b2[0];
    float2 cb = *reinterpret_cast<const float2*>(g_C + 2 * lane);
    float s = 1.0f / (1.0f + expf(-(a0 + base + cb.x)))
            + 1.0f / (1.0f + expf(-(a1 + base + cb.y)));
    #pragma unroll
    for (int off = 16; off; off >>= 1)
        s += __shfl_down_sync(0xffffffffu, s, off);
    if (lane == 0)
        out[(i0 + wi) * 64 + (j0 + wj)] = s * (1.0f / 64.0f);
}

// ---------------------------------------------------------------------------
extern "C" void kernel_launch(void* const* d_in, const int* in_sizes, int n_in,
                              void* d_out, int out_size)
{
    const float* state  = (const float*)d_in[0];
    const float* action = (const float*)d_in[1];
    const float* embed  = (const float*)d_in[2];
    const float* W1     = (const float*)d_in[3];
    const float* b1     = (const float*)d_in[4];
    const float* W2     = (const float*)d_in[5];
    const float* b2     = (const float*)d_in[6];
    float* out = (float*)d_out;

    dim3 g1(64, 3);
    gemm_kernel<<<g1, 256>>>(state, action, embed, W1, b1);
    pre_kernel<<<3, 256>>>(W2);

    const int smem = (2048 + 4096 + 2048 + 4096) * sizeof(float); // 49152 B
    cudaFuncSetAttribute(score_kernel, cudaFuncAttributeMaxDynamicSharedMemorySize, smem);
    score_kernel<<<512, 256, smem>>>(W2, b2, out);
}

// round 10
// speedup vs baseline: 1.3545x; 1.1726x over previous
#include <cuda_runtime.h>
#include <math.h>

#define DIMK 512
#define HD   1024

typedef unsigned long long ull;

// 4-way k-split partials (chunk c covers k in [c*128, c*128+128))
__device__ __align__(16) float g_caus4[4 * 64 * HD];
__device__ __align__(16) float g_eff4 [4 * 64 * HD];
__device__ __align__(16) float g_ctxT4[4 * HD * 64];   // transposed [h][b]
// reduced buffers
__device__ __align__(16) float g_caus[64 * HD];        // includes +b1
__device__ __align__(16) float g_eff [64 * HD];
__device__ __align__(16) float g_ctxT[HD * 64];
// separable linear parts (w' = 0.5*W2)
__device__ float g_A[64];
__device__ float g_B[64];
__device__ float g_C[64];

// ---------------------------------------------------------------------------
// Phase 1: three 64x512 @ 512x1024 GEMMs. grid=(128,3): x>>2 = 32-col tile,
// x&3 = k-chunk (128). Both X and W tiles fully staged in smem (48KB) so the
// FMA loop has zero global-latency dependence. 384 blocks.
// ---------------------------------------------------------------------------
__global__ void __launch_bounds__(256) gemm_kernel(
    const float* __restrict__ state, const float* __restrict__ action,
    const float* __restrict__ embed, const float* __restrict__ W1)
{
    const int slot    = blockIdx.y;
    const int colbase = (blockIdx.x >> 2) * 32;
    const int chunk   = blockIdx.x & 3;
    const int kbase   = chunk * 128;

    const float* W = W1 + slot * DIMK * HD;

    __shared__ float Xs[64][128];   // 32 KB
    __shared__ float Ws[128][32];   // 16 KB

    const int tid = threadIdx.x;
    const int tx  = tid & 15;
    const int ty  = tid >> 4;

    // stage X tile [64][128]
    for (int idx = tid; idx < 2048; idx += 256) {
        int row = idx >> 5, q = idx & 31;
        int gc  = kbase + q * 4;
        float4 v;
        if (slot < 2) {
            v = *reinterpret_cast<const float4*>(embed + row * DIMK + gc);
        } else {
            float4 s4 = *reinterpret_cast<const float4*>(state  + row * DIMK + gc);
            float4 a4 = *reinterpret_cast<const float4*>(action + row * DIMK + gc);
            v = make_float4(s4.x + a4.x, s4.y + a4.y, s4.z + a4.z, s4.w + a4.w);
        }
        *reinterpret_cast<float4*>(&Xs[row][q * 4]) = v;
    }
    // stage W tile [128][32]
    for (int idx = tid; idx < 1024; idx += 256) {
        int k = idx >> 3, c4 = idx & 7;
        *reinterpret_cast<float4*>(&Ws[k][4 * c4]) =
            *reinterpret_cast<const float4*>(W + (kbase + k) * HD + colbase + 4 * c4);
    }
    __syncthreads();

    float acc[4][2] = {};
    #pragma unroll 8
    for (int k = 0; k < 128; k++) {
        float2 w = *reinterpret_cast<const float2*>(&Ws[k][2 * tx]);
        #pragma unroll
        for (int r = 0; r < 4; r++) {
            float xv = Xs[ty + 16 * r][k];
            acc[r][0] = fmaf(xv, w.x, acc[r][0]);
            acc[r][1] = fmaf(xv, w.y, acc[r][1]);
        }
    }

    #pragma unroll
    for (int r = 0; r < 4; r++) {
        int row = ty + 16 * r;
        int c0  = colbase + 2 * tx;
        if (slot == 0) {
            float* dst = g_caus4 + chunk * 64 * HD;
            dst[row * HD + c0]     = acc[r][0];
            dst[row * HD + c0 + 1] = acc[r][1];
        } else if (slot == 1) {
            float* dst = g_eff4 + chunk * 64 * HD;
            dst[row * HD + c0]     = acc[r][0];
            dst[row * HD + c0 + 1] = acc[r][1];
        } else {
            float* dst = g_ctxT4 + chunk * HD * 64;
            dst[c0 * 64 + row]       = acc[r][0];
            dst[(c0 + 1) * 64 + row] = acc[r][1];
        }
    }
}

// ---------------------------------------------------------------------------
// Phase 1.25: reduce 4 partials -> single buffers (b1 folded into caus).
// grid = 192 blocks x 256 threads, 1 float4 per thread.
// ---------------------------------------------------------------------------
__global__ void __launch_bounds__(256) reduce_kernel(const float* __restrict__ b1)
{
    const int slot = blockIdx.x >> 6;           // 64 blocks per slot
    const int gidx = (blockIdx.x & 63) * 256 + threadIdx.x;   // float4 index < 16384
    const int N = 64 * HD / 4;
    if (gidx >= N) return;

    const float4* s0; const float4* s1; const float4* s2; const float4* s3;
    float4* dst;
    if (slot == 0) {
        s0 = (const float4*)g_caus4; dst = (float4*)g_caus;
    } else if (slot == 1) {
        s0 = (const float4*)g_eff4;  dst = (float4*)g_eff;
    } else {
        s0 = (const float4*)g_ctxT4; dst = (float4*)g_ctxT;
    }
    s1 = s0 + N; s2 = s0 + 2 * N; s3 = s0 + 3 * N;

    float4 a = s0[gidx], b = s1[gidx], c = s2[gidx], d = s3[gidx];
    float4 r = make_float4(a.x + b.x + c.x + d.x, a.y + b.y + c.y + d.y,
                           a.z + b.z + c.z + d.z, a.w + b.w + c.w + d.w);
    if (slot == 0) {
        float4 bb = *reinterpret_cast<const float4*>(b1 + ((gidx * 4) & (HD - 1)));
        r.x += bb.x; r.y += bb.y; r.z += bb.z; r.w += bb.w;
    }
    dst[gidx] = r;
}

// ---------------------------------------------------------------------------
// Phase 1.5: separable linear parts A_i, B_j, C_b  (w' = 0.5*W2)
// ---------------------------------------------------------------------------
__global__ void __launch_bounds__(256) pre_kernel(const float* __restrict__ W2)
{
    const int slot = blockIdx.x;
    const int tid  = threadIdx.x;
    if (slot < 2) {
        const float* P = slot == 0 ? g_caus : g_eff;
        float* dst = slot == 0 ? g_A : g_B;
        int w = tid >> 5, lane = tid & 31;
        #pragma unroll
        for (int m = 0; m < 8; m++) {
            int row = w * 8 + m;
            float s = 0.f;
            for (int h = lane; h < HD; h += 32)
                s += P[row * HD + h] * (0.5f * W2[h]);
            #pragma unroll
            for (int off = 16; off; off >>= 1)
                s += __shfl_down_sync(0xffffffffu, s, off);
            if (lane == 0) dst[row] = s;
        }
    } else {
        __shared__ float red[256];
        int b = tid & 63, part = tid >> 6;
        float s = 0.f;
        for (int h = part * 256; h < part * 256 + 256; h++)
            s += g_ctxT[h * 64 + b] * (0.5f * W2[h]);
        red[tid] = s;
        __syncthreads();
        if (tid < 64)
            g_C[tid] = red[tid] + red[tid + 64] + red[tid + 128] + red[tid + 192];
    }
}

// ---------------------------------------------------------------------------
// f32x2 packed helpers
// ---------------------------------------------------------------------------
__device__ __forceinline__ ull pack2(float a, float b) {
    ull r;
    asm("mov.b64 %0, {%1, %2};" : "=l"(r)
        : "r"(__float_as_uint(a)), "r"(__float_as_uint(b)));
    return r;
}
__device__ __forceinline__ void unpack2(ull v, float& a, float& b) {
    unsigned int x, y;
    asm("mov.b64 {%0, %1}, %2;" : "=r"(x), "=r"(y) : "l"(v));
    a = __uint_as_float(x); b = __uint_as_float(y);
}
__device__ __forceinline__ ull add2(ull a, ull b) {
    ull r; asm("add.rn.f32x2 %0, %1, %2;" : "=l"(r) : "l"(a), "l"(b)); return r;
}
__device__ __forceinline__ ull mul2(ull a, ull b) {
    ull r; asm("mul.rn.f32x2 %0, %1, %2;" : "=l"(r) : "l"(a), "l"(b)); return r;
}
__device__ __forceinline__ ull fma2(ull a, ull b, ull c) {
    ull r; asm("fma.rn.f32x2 %0, %1, %2, %3;" : "=l"(r) : "l"(a), "l"(b), "l"(c)); return r;
}
__device__ __forceinline__ float tanh_ap(float x) {
    float r; asm("tanh.approx.f32 %0, %1;" : "=f"(r) : "f"(x)); return r;
}

// ---------------------------------------------------------------------------
// Phase 2: logit = (A_i + B_j + C_b + b2) + sum_h xw'*tanh(...)
// Inner loop: 6 f32x2 + 2 tanh per lane-k. Staging reads single buffers.
// ---------------------------------------------------------------------------
__global__ void __launch_bounds__(256) score_kernel(
    const float* __restrict__ W2, const float* __restrict__ b2,
    float* __restrict__ out)
{
    extern __shared__ float sm[];
    float* caus_s = sm;              // 2 * 1024
    float* eff_s  = sm + 2048;       // 4 * 1024
    float* w2p    = sm + 6144;       // 2048 (1024 pairs of 0.5*W2, duplicated)
    float* ctx_s  = sm + 8192;       // 64 * 64

    const int tid = threadIdx.x;
    const int i0  = (blockIdx.x >> 4) * 2;   // 32 i-tiles
    const int j0  = (blockIdx.x & 15) * 4;   // 16 j-tiles

    for (int lin = tid; lin < 2048; lin += 256) {
        int r = lin >> 10, c = lin & 1023;
        caus_s[lin] = g_caus[(i0 + r) * HD + c];
    }
    for (int lin = tid; lin < 4096; lin += 256) {
        int r = lin >> 10, c = lin & 1023;
        eff_s[lin]  = g_eff[(j0 + r) * HD + c];
    }
    for (int lin = tid; lin < 1024; lin += 256) {
        float v = 0.5f * W2[lin];
        w2p[2 * lin]     = v;
        w2p[2 * lin + 1] = v;
    }

    const int w    = tid >> 5;
    const int lane = tid & 31;
    const int wi   = w >> 2, wj = w & 3;
    const float* cs = caus_s + wi * 1024;
    const float* es = eff_s  + wj * 1024;
    const ull*  ctxp = reinterpret_cast<const ull*>(ctx_s);

    const ull C0 = pack2(0.7978845608f, 0.7978845608f);
    const ull C1 = pack2(0.0356774081f, 0.0356774081f);
    ull acc = pack2(0.f, 0.f);

    for (int ht = 0; ht < HD; ht += 64) {
        __syncthreads();   // covers initial staging on first iter
        for (int lin = tid * 4; lin < 64 * 64; lin += 256 * 4) {
            *reinterpret_cast<float4*>(ctx_s + lin) =
                *reinterpret_cast<const float4*>(g_ctxT + ht * 64 + lin);
        }
        __syncthreads();

        const float* w2row = w2p + 2 * ht;
        #pragma unroll 4
        for (int k = 0; k < 64; k += 4) {
            float4 cv = *reinterpret_cast<const float4*>(cs + ht + k);
            float4 ev = *reinterpret_cast<const float4*>(es + ht + k);
            float ce[4] = {cv.x + ev.x, cv.y + ev.y, cv.z + ev.z, cv.w + ev.w};
            #pragma unroll
            for (int q = 0; q < 4; q++) {
                ull ce2 = pack2(ce[q], ce[q]);
                ull hw2 = *reinterpret_cast<const ull*>(w2row + 2 * (k + q));
                ull c2  = ctxp[(k + q) * 32 + lane];
                ull x2  = add2(ce2, c2);
                ull u2  = mul2(x2, x2);
                ull p2  = fma2(u2, C1, C0);
                ull in2 = mul2(x2, p2);
                float ia, ib; unpack2(in2, ia, ib);
                ull t2  = pack2(tanh_ap(ia), tanh_ap(ib));
                ull xw2 = mul2(x2, hw2);
                acc = fma2(xw2, t2, acc);
            }
        }
    }

    float a0, a1; unpack2(acc, a0, a1);
    float base = g_A[i0 + wi] + g_B[j0 + wj] + b2[0];
    float2 cb = *reinterpret_cast<const float2*>(g_C + 2 * lane);
    float s = 1.0f / (1.0f + expf(-(a0 + base + cb.x)))
            + 1.0f / (1.0f + expf(-(a1 + base + cb.y)));
    #pragma unroll
    for (int off = 16; off; off >>= 1)
        s += __shfl_down_sync(0xffffffffu, s, off);
    if (lane == 0)
        out[(i0 + wi) * 64 + (j0 + wj)] = s * (1.0f / 64.0f);
}

// ---------------------------------------------------------------------------
extern "C" void kernel_launch(void* const* d_in, const int* in_sizes, int n_in,
                              void* d_out, int out_size)
{
    const float* state  = (const float*)d_in[0];
    const float* action = (const float*)d_in[1];
    const float* embed  = (const float*)d_in[2];
    const float* W1     = (const float*)d_in[3];
    const float* b1     = (const float*)d_in[4];
    const float* W2     = (const float*)d_in[5];
    const float* b2     = (const float*)d_in[6];
    float* out = (float*)d_out;

    dim3 g1(128, 3);
    gemm_kernel<<<g1, 256>>>(state, action, embed, W1);
    reduce_kernel<<<192, 256>>>(b1);
    pre_kernel<<<3, 256>>>(W2);

    const int smem = (2048 + 4096 + 2048 + 4096) * sizeof(float); // 49152 B
    cudaFuncSetAttribute(score_kernel, cudaFuncAttributeMaxDynamicSharedMemorySize, smem);
    score_kernel<<<512, 256, smem>>>(W2, b2, out);
}